// round 9
// baseline (speedup 1.0000x reference)
#include <cuda_runtime.h>
#include <cuda_fp16.h>

// Problem: B=2, C=4, D=64, H=256, W=256
#define HW    65536        // H*W
#define DHW   4194304      // D*H*W
#define DHW4  1048576      // DHW/4
#define DHW8  524288       // DHW/8
#define NQ    2097152      // pass-2 threads (4 voxels each)
#define NQ8   1048576      // pass-1 threads (8 voxels each)
#define NELEM 25165824.0   // B*(C-1)*DHW

// Planar scratch: A = half2(p1,p2)/voxel, B = half(p3)/voxel, T = uint8/voxel
__device__ __align__(16) __half2       g_A[2 * DHW];
__device__ __align__(16) __half        g_B[2 * DHW];
__device__ __align__(16) unsigned char g_T[2 * DHW];
__device__ double   g_acc;
__device__ unsigned g_done = 0;

__device__ __forceinline__ unsigned h2u(__half2 h) { return *(unsigned*)&h; }
__device__ __forceinline__ __half2 u2h(unsigned u) { return *(__half2*)&u; }

// ---------------- Pass 1: softmax (8 voxels/thread) + target byte-encode -----
__global__ void __launch_bounds__(256)
softmax_kernel(const float* __restrict__ logits, const int* __restrict__ targets) {
    int t = blockIdx.x * blockDim.x + threadIdx.x;
    if (t == 0) g_acc = 0.0;
    if (t >= NQ8) return;
    int b  = t >> 19;
    int v8 = t & (DHW8 - 1);
    const float4* L = (const float4*)logits;
    size_t base4 = (size_t)b * 4 * DHW4 + ((size_t)v8 << 1);

    uint4 a4[2]; uint4 b4; uint2 t2;
    unsigned* bw = (unsigned*)&b4;
#pragma unroll
    for (int g = 0; g < 2; ++g) {
        float4 x0 = L[base4 + 0 * DHW4 + g];
        float4 x1 = L[base4 + 1 * DHW4 + g];
        float4 x2 = L[base4 + 2 * DHW4 + g];
        float4 x3 = L[base4 + 3 * DHW4 + g];
        float4 p1, p2, p3;
#define SM1(comp) {                                                        \
            float e1 = __expf(x1.comp - x0.comp);                          \
            float e2 = __expf(x2.comp - x0.comp);                          \
            float e3 = __expf(x3.comp - x0.comp);                          \
            float inv = __frcp_rn(1.f + e1 + e2 + e3);                     \
            p1.comp = e1 * inv; p2.comp = e2 * inv; p3.comp = e3 * inv; }
        SM1(x) SM1(y) SM1(z) SM1(w)
#undef SM1
        a4[g].x = h2u(__floats2half2_rn(p1.x, p2.x));
        a4[g].y = h2u(__floats2half2_rn(p1.y, p2.y));
        a4[g].z = h2u(__floats2half2_rn(p1.z, p2.z));
        a4[g].w = h2u(__floats2half2_rn(p1.w, p2.w));
        bw[2 * g + 0] = h2u(__floats2half2_rn(p3.x, p3.y));
        bw[2 * g + 1] = h2u(__floats2half2_rn(p3.z, p3.w));
    }
    size_t v = ((size_t)b * DHW) + ((size_t)v8 << 3);
    *(uint4*)(g_A + v)     = a4[0];
    *(uint4*)(g_A + v + 4) = a4[1];
    *(uint4*)(g_B + v)     = b4;
    const int4* T4 = (const int4*)targets + ((size_t)b * DHW4) + ((size_t)v8 << 1);
    int4 ta = T4[0], tb = T4[1];
    t2.x = (unsigned)ta.x | ((unsigned)ta.y << 8) | ((unsigned)ta.z << 16) | ((unsigned)ta.w << 24);
    t2.y = (unsigned)tb.x | ((unsigned)tb.y << 8) | ((unsigned)tb.z << 16) | ((unsigned)tb.w << 24);
    *(uint2*)(g_T + v) = t2;
}

// ---------------- Pass 2: stencil + loss + reduction -------------------------
__global__ void __launch_bounds__(256, 5)
loss_kernel(float* __restrict__ out) {
    int t  = blockIdx.x * blockDim.x + threadIdx.x;
    int w4 = t & 63;
    int h  = (t >> 6) & 255;
    int d  = (t >> 14) & 63;
    int b  = t >> 20;
    size_t v = (size_t)d * HW + h * 256 + (w4 << 2);

    const __half2*       A  = g_A + (size_t)b * DHW;
    const __half*        Bp = g_B + (size_t)b * DHW;
    const unsigned char* Tb = g_T + (size_t)b * DHW;

    const bool d0ok = (d > 0), d1ok = (d < 63);
    const bool h0ok = (h > 0), h1ok = (h < 255);
    const bool w0ok = (w4 > 0), w1ok = (w4 < 63);
    const uint4 z4 = make_uint4(0, 0, 0, 0);
    const uint2 z2 = make_uint2(0, 0);

    // ---- loads (front-batched) ----
    uint4 Ac  = *(const uint4*)(A + v);
    uint4 Adm = d0ok ? *(const uint4*)(A + v - HW)  : z4;
    uint4 Adp = d1ok ? *(const uint4*)(A + v + HW)  : z4;
    uint4 Ahm = h0ok ? *(const uint4*)(A + v - 256) : z4;
    uint4 Ahp = h1ok ? *(const uint4*)(A + v + 256) : z4;
    unsigned lfA = w0ok ? *(const unsigned*)(A + v - 1) : 0u;
    unsigned rtA = w1ok ? *(const unsigned*)(A + v + 4) : 0u;

    uint2 Bc  = *(const uint2*)(Bp + v);
    uint2 Bdm = d0ok ? *(const uint2*)(Bp + v - HW)  : z2;
    uint2 Bdp = d1ok ? *(const uint2*)(Bp + v + HW)  : z2;
    uint2 Bhm = h0ok ? *(const uint2*)(Bp + v - 256) : z2;
    uint2 Bhp = h1ok ? *(const uint2*)(Bp + v + 256) : z2;
    unsigned bL = w0ok ? *(const unsigned*)(Bp + v - 2) : 0u;
    unsigned bR = w1ok ? *(const unsigned*)(Bp + v + 4) : 0u;

    unsigned tc4 = *(const unsigned*)(Tb + v);
    unsigned tdm = d0ok ? *(const unsigned*)(Tb + v - HW)  : 0u;
    unsigned tdp = d1ok ? *(const unsigned*)(Tb + v + HW)  : 0u;
    unsigned thm = h0ok ? *(const unsigned*)(Tb + v - 256) : 0u;
    unsigned thp = h1ok ? *(const unsigned*)(Tb + v + 256) : 0u;
    unsigned twL = w0ok ? *(const unsigned*)(Tb + v - 4)   : 0u;
    unsigned twR = w1ok ? *(const unsigned*)(Tb + v + 4)   : 0u;

    // ---- A stencil: per voxel j, half2 = classes (1,2) ----
    const __half2 m6 = __floats2half2_rn(-6.f, -6.f);
    const __half2* cA = (const __half2*)&Ac;
    __half2 sA[4];
    {
        const __half2* dm = (const __half2*)&Adm;
        const __half2* dp = (const __half2*)&Adp;
        const __half2* hm = (const __half2*)&Ahm;
        const __half2* hp = (const __half2*)&Ahp;
#pragma unroll
        for (int j = 0; j < 4; ++j) {
            __half2 lf = (j == 0) ? u2h(lfA) : cA[j - 1];
            __half2 rt = (j == 3) ? u2h(rtA) : cA[j + 1];
            __half2 s = __hadd2(__hadd2(dm[j], dp[j]), __hadd2(hm[j], hp[j]));
            s = __hadd2(s, __hadd2(lf, rt));
            sA[j] = __hfma2(cA[j], m6, s);
        }
    }

    // ---- B stencil: pairs (v0,v1) and (v2,v3), class 3 ----
    unsigned L0  = __byte_perm(Bc.x, bL, 0x1076);   // (B[v-1], v0)
    unsigned mid = __byte_perm(Bc.x, Bc.y, 0x5432); // (v1, v2)
    unsigned R1  = __byte_perm(Bc.y, bR, 0x5432);   // (v3, B[v+4])
    __half2 sB0 = __hadd2(__hadd2(u2h(Bdm.x), u2h(Bdp.x)),
                          __hadd2(u2h(Bhm.x), u2h(Bhp.x)));
    sB0 = __hadd2(sB0, __hadd2(u2h(L0), u2h(mid)));
    sB0 = __hfma2(u2h(Bc.x), m6, sB0);
    __half2 sB1 = __hadd2(__hadd2(u2h(Bdm.y), u2h(Bdp.y)),
                          __hadd2(u2h(Bhm.y), u2h(Bhp.y)));
    sB1 = __hadd2(sB1, __hadd2(u2h(mid), u2h(R1)));
    sB1 = __hfma2(u2h(Bc.y), m6, sB1);

    // ---- byte-SIMD target |Laplacian| per class (bytes 0..6) ----
    unsigned lt4 = __byte_perm(tc4, twL, 0x2107);
    unsigned rt4 = __byte_perm(tc4, twR, 0x4321);
    const unsigned ONE = 0x01010101u;
    unsigned absT[3];
#pragma unroll
    for (int c = 0; c < 3; ++c) {
        unsigned cc = ONE * (unsigned)(c + 1);
        unsigned cnt = __vsub4(0u, __vcmpeq4(tdm, cc));
        cnt = __vsub4(cnt, __vcmpeq4(tdp, cc));
        cnt = __vsub4(cnt, __vcmpeq4(thm, cc));
        cnt = __vsub4(cnt, __vcmpeq4(thp, cc));
        cnt = __vsub4(cnt, __vcmpeq4(lt4, cc));
        cnt = __vsub4(cnt, __vcmpeq4(rt4, cc));
        unsigned e = __vcmpeq4(tc4, cc);           // 0xFF where center == class
        absT[c] = (cnt & ~e) | (__vsub4(0x06060606u, cnt) & e);
    }

    // ---- bytes(0..6) -> fp16 high-byte via PRMT table ----
    // PRMT selector = low 16 bits, one NIBBLE per output byte: compact the
    // four byte-values of absT into nibbles first.
    const unsigned tblA = 0x42403C00u;  // high bytes of half(0..3)
    const unsigned tblB = 0x00464544u;  // high bytes of half(4..6)
#define TBL_LOOKUP(dst, a) {                                               \
        unsigned s1_ = (a) | ((a) >> 4);            /* b0|b1<<4, b2|b3<<4 */\
        unsigned sel_ = __byte_perm(s1_, 0u, 0x4420); /* nibble-packed */   \
        dst = __byte_perm(tblA, tblB, sel_); }
    unsigned hi1, hi2, hi3;
    TBL_LOOKUP(hi1, absT[0])
    TBL_LOOKUP(hi2, absT[1])
    TBL_LOOKUP(hi3, absT[2])
#undef TBL_LOOKUP

    __half2 accA = __floats2half2_rn(0.f, 0.f);
    __half2 accB = accA;
#pragma unroll
    for (int j = 0; j < 4; ++j) {
        unsigned pair = __byte_perm(hi1, hi2, (unsigned)(j | ((4 + j) << 4)));
        __half2 t12 = u2h(__byte_perm(pair, 0u, 0x1404));
        __half2 dd = __hsub2(__habs2(sA[j]), t12);
        accA = __hfma2(dd, dd, accA);
    }
    {
        __half2 t3a = u2h(__byte_perm(hi3, 0u, 0x1404));  // (v0, v1)
        __half2 t3b = u2h(__byte_perm(hi3, 0u, 0x3424));  // (v2, v3)
        __half2 d0 = __hsub2(__habs2(sB0), t3a);
        accB = __hfma2(d0, d0, accB);
        __half2 d1 = __hsub2(__habs2(sB1), t3b);
        accB = __hfma2(d1, d1, accB);
    }
    float2 fa = __half22float2(accA);
    float2 fb = __half22float2(accB);
    float acc = (fa.x + fa.y) + (fb.x + fb.y);

    // ---- block reduction -> double atomic -> last-block finalize ----
#pragma unroll
    for (int o = 16; o; o >>= 1) acc += __shfl_down_sync(0xffffffffu, acc, o);
    __shared__ float ws[8];
    __shared__ unsigned ticket;
    int lane = threadIdx.x & 31, wid = threadIdx.x >> 5;
    if (lane == 0) ws[wid] = acc;
    __syncthreads();
    if (wid == 0) {
        acc = (lane < 8) ? ws[lane] : 0.f;
#pragma unroll
        for (int o = 4; o; o >>= 1) acc += __shfl_down_sync(0xffffffffu, acc, o);
        if (lane == 0) {
            atomicAdd(&g_acc, (double)acc);
            __threadfence();
            ticket = atomicAdd(&g_done, 1u);
        }
    }
    __syncthreads();
    if (threadIdx.x == 0 && ticket == gridDim.x - 1) {
        double total = atomicAdd(&g_acc, 0.0);
        out[0] = (float)(total * (1.0 / NELEM));
        g_done = 0;
    }
}

extern "C" void kernel_launch(void* const* d_in, const int* in_sizes, int n_in,
                              void* d_out, int out_size) {
    const float* logits  = (const float*)d_in[0];
    const int*   targets = (const int*)d_in[1];
    float* out = (float*)d_out;

    softmax_kernel<<<NQ8 / 256, 256>>>(logits, targets);
    loss_kernel<<<NQ / 256, 256>>>(out);
}

// round 10
// speedup vs baseline: 1.0366x; 1.0366x over previous
#include <cuda_runtime.h>
#include <cuda_fp16.h>

// Problem: B=2, C=4, D=64, H=256, W=256
#define HW    65536        // H*W
#define DHW   4194304      // D*H*W
#define DHW4  1048576      // DHW/4
#define NQ    2097152      // pass-1 threads (4 voxels each)
#define NQ2   1048576      // pass-2 threads (8 voxels each)
#define NELEM 25165824.0   // B*(C-1)*DHW

// Planar scratch: A = half2(p1,p2)/voxel, B = half(p3)/voxel, T = uint8/voxel
__device__ __align__(16) __half2       g_A[2 * DHW];
__device__ __align__(16) __half        g_B[2 * DHW];
__device__ __align__(16) unsigned char g_T[2 * DHW];
__device__ double   g_acc;
__device__ unsigned g_done = 0;

__device__ __forceinline__ unsigned h2u(__half2 h) { return *(unsigned*)&h; }
__device__ __forceinline__ __half2 u2h(unsigned u) { return *(__half2*)&u; }

// ---------------- Pass 1: softmax (4 voxels/thread) + target byte-encode -----
__global__ void __launch_bounds__(256)
softmax_kernel(const float* __restrict__ logits, const int* __restrict__ targets) {
    int t = blockIdx.x * blockDim.x + threadIdx.x;
    if (t == 0) g_acc = 0.0;
    if (t >= NQ) return;
    int b  = t >> 20;
    int v4 = t & (DHW4 - 1);
    const float4* L = (const float4*)logits + (size_t)b * 4 * DHW4 + v4;
    float4 x0 = L[0 * DHW4];
    float4 x1 = L[1 * DHW4];
    float4 x2 = L[2 * DHW4];
    float4 x3 = L[3 * DHW4];
    float4 p1, p2, p3;
#define SM1(comp) {                                                       \
        float a = x0.comp, bb = x1.comp, c = x2.comp, dd = x3.comp;       \
        float m  = fmaxf(fmaxf(a, bb), fmaxf(c, dd));                     \
        float e0 = __expf(a - m), e1 = __expf(bb - m);                    \
        float e2 = __expf(c - m), e3 = __expf(dd - m);                    \
        float inv = __frcp_rn(e0 + e1 + e2 + e3);                        \
        p1.comp = e1 * inv; p2.comp = e2 * inv; p3.comp = e3 * inv; }
    SM1(x) SM1(y) SM1(z) SM1(w)
#undef SM1
    size_t v = ((size_t)b * DHW) + ((size_t)v4 << 2);
    uint4 a4;
    a4.x = h2u(__floats2half2_rn(p1.x, p2.x));
    a4.y = h2u(__floats2half2_rn(p1.y, p2.y));
    a4.z = h2u(__floats2half2_rn(p1.z, p2.z));
    a4.w = h2u(__floats2half2_rn(p1.w, p2.w));
    *(uint4*)(g_A + v) = a4;
    uint2 b2;
    b2.x = h2u(__floats2half2_rn(p3.x, p3.y));
    b2.y = h2u(__floats2half2_rn(p3.z, p3.w));
    *(uint2*)(g_B + v) = b2;
    int4 tt = *((const int4*)targets + ((size_t)b * DHW4) + v4);
    unsigned tw = (unsigned)tt.x | ((unsigned)tt.y << 8)
                | ((unsigned)tt.z << 16) | ((unsigned)tt.w << 24);
    *(unsigned*)(g_T + v) = tw;
}

// ---------------- Pass 2: stencil + loss + reduction (8 voxels/thread) -------
__global__ void __launch_bounds__(256, 4)
loss_kernel(float* __restrict__ out) {
    int t  = blockIdx.x * blockDim.x + threadIdx.x;
    int w8 = t & 31;
    int h  = (t >> 5) & 255;
    int d  = (t >> 13) & 63;
    int b  = t >> 19;
    size_t v = (size_t)d * HW + h * 256 + (w8 << 3);

    const __half2*       A  = g_A + (size_t)b * DHW;
    const __half*        Bp = g_B + (size_t)b * DHW;
    const unsigned char* Tb = g_T + (size_t)b * DHW;

    const bool d0ok = (d > 0), d1ok = (d < 63);
    const bool h0ok = (h > 0), h1ok = (h < 255);
    const bool w0ok = (w8 > 0), w1ok = (w8 < 31);
    const uint4 z4 = make_uint4(0, 0, 0, 0);
    const uint2 z2 = make_uint2(0, 0);
    const __half2 m6 = __floats2half2_rn(-6.f, -6.f);

    float acc = 0.f;

    // ================= A phase: classes (1,2) =================
    __half2 sA[8];
    {
        uint4 Ac[2], Adm[2], Adp[2], Ahm[2], Ahp[2];
#pragma unroll
        for (int g = 0; g < 2; ++g) {
            Ac[g]  = *(const uint4*)(A + v + 4 * g);
            Adm[g] = d0ok ? *(const uint4*)(A + v - HW  + 4 * g) : z4;
            Adp[g] = d1ok ? *(const uint4*)(A + v + HW  + 4 * g) : z4;
            Ahm[g] = h0ok ? *(const uint4*)(A + v - 256 + 4 * g) : z4;
            Ahp[g] = h1ok ? *(const uint4*)(A + v + 256 + 4 * g) : z4;
        }
        unsigned lfA = w0ok ? *(const unsigned*)(A + v - 1) : 0u;
        unsigned rtA = w1ok ? *(const unsigned*)(A + v + 8) : 0u;
        const __half2* cA = (const __half2*)Ac;
        const __half2* dm = (const __half2*)Adm;
        const __half2* dp = (const __half2*)Adp;
        const __half2* hm = (const __half2*)Ahm;
        const __half2* hp = (const __half2*)Ahp;
#pragma unroll
        for (int j = 0; j < 8; ++j) {
            __half2 lf = (j == 0) ? u2h(lfA) : cA[j - 1];
            __half2 rt = (j == 7) ? u2h(rtA) : cA[j + 1];
            __half2 s = __hadd2(__hadd2(dm[j], dp[j]), __hadd2(hm[j], hp[j]));
            s = __hadd2(s, __hadd2(lf, rt));
            sA[j] = __hfma2(cA[j], m6, s);
        }
    }

    // ================= B phase: class 3 =================
    __half2 sB[4];
    {
        uint4 Bc  = *(const uint4*)(Bp + v);
        uint4 Bdm = d0ok ? *(const uint4*)(Bp + v - HW)  : z4;
        uint4 Bdp = d1ok ? *(const uint4*)(Bp + v + HW)  : z4;
        uint4 Bhm = h0ok ? *(const uint4*)(Bp + v - 256) : z4;
        uint4 Bhp = h1ok ? *(const uint4*)(Bp + v + 256) : z4;
        unsigned bL = w0ok ? *(const unsigned*)(Bp + v - 2) : 0u;
        unsigned bR = w1ok ? *(const unsigned*)(Bp + v + 8) : 0u;

        unsigned shl[5], shr[5];
        // pairs: shifted sequences. shl[k] = (left of v2k, left of v2k+1)
        shl[0] = __byte_perm(Bc.x, bL,   0x1076);  // (B[v-1], v0)
        shl[1] = __byte_perm(Bc.x, Bc.y, 0x5432);  // (v1, v2)
        shl[2] = __byte_perm(Bc.y, Bc.z, 0x5432);  // (v3, v4)
        shl[3] = __byte_perm(Bc.z, Bc.w, 0x5432);  // (v5, v6)
        shl[4] = __byte_perm(Bc.w, bR,   0x5432);  // (v7, B[v+8])
        const unsigned* cw  = (const unsigned*)&Bc;
        const unsigned* dmw = (const unsigned*)&Bdm;
        const unsigned* dpw = (const unsigned*)&Bdp;
        const unsigned* hmw = (const unsigned*)&Bhm;
        const unsigned* hpw = (const unsigned*)&Bhp;
#pragma unroll
        for (int k = 0; k < 4; ++k) {
            __half2 s = __hadd2(__hadd2(u2h(dmw[k]), u2h(dpw[k])),
                                __hadd2(u2h(hmw[k]), u2h(hpw[k])));
            s = __hadd2(s, __hadd2(u2h(shl[k]), u2h(shl[k + 1])));
            sB[k] = __hfma2(u2h(cw[k]), m6, s);
        }
    }

    // ================= T phase: byte-SIMD target |Laplacian| =================
    unsigned absT[3][2];
    unsigned tcw[2];
    {
        uint2 Tc  = *(const uint2*)(Tb + v);
        uint2 Tdm = d0ok ? *(const uint2*)(Tb + v - HW)  : z2;
        uint2 Tdp = d1ok ? *(const uint2*)(Tb + v + HW)  : z2;
        uint2 Thm = h0ok ? *(const uint2*)(Tb + v - 256) : z2;
        uint2 Thp = h1ok ? *(const uint2*)(Tb + v + 256) : z2;
        unsigned twL = w0ok ? *(const unsigned*)(Tb + v - 4) : 0u;
        unsigned twR = w1ok ? *(const unsigned*)(Tb + v + 8) : 0u;

        unsigned lt[2], rt[2];
        lt[0] = __byte_perm(Tc.x, twL,  0x2107);   // (t[v-1], t0, t1, t2)
        lt[1] = __byte_perm(Tc.y, Tc.x, 0x2107);   // (t3, t4, t5, t6)
        rt[0] = __byte_perm(Tc.x, Tc.y, 0x4321);   // (t1, t2, t3, t4)
        rt[1] = __byte_perm(Tc.y, twR,  0x4321);   // (t5, t6, t7, t[v+8])
        tcw[0] = Tc.x; tcw[1] = Tc.y;
        const unsigned* dmw = (const unsigned*)&Tdm;
        const unsigned* dpw = (const unsigned*)&Tdp;
        const unsigned* hmw = (const unsigned*)&Thm;
        const unsigned* hpw = (const unsigned*)&Thp;
        const unsigned ONE = 0x01010101u;
#pragma unroll
        for (int c = 0; c < 3; ++c) {
            unsigned cc = ONE * (unsigned)(c + 1);
#pragma unroll
            for (int w = 0; w < 2; ++w) {
                unsigned cnt = __vsub4(0u, __vcmpeq4(dmw[w], cc));
                cnt = __vsub4(cnt, __vcmpeq4(dpw[w], cc));
                cnt = __vsub4(cnt, __vcmpeq4(hmw[w], cc));
                cnt = __vsub4(cnt, __vcmpeq4(hpw[w], cc));
                cnt = __vsub4(cnt, __vcmpeq4(lt[w], cc));
                cnt = __vsub4(cnt, __vcmpeq4(rt[w], cc));
                unsigned e6 = __vcmpeq4(tcw[w], cc) & 0x06060606u;
                absT[c][w] = __vabsdiffs4(cnt, e6);
            }
        }
    }

    // ================= convert + accumulate =================
#pragma unroll
    for (int w = 0; w < 2; ++w) {
#pragma unroll
        for (int j = 0; j < 4; ++j) {
            int vox = 4 * w + j;
            float2 f12 = __half22float2(__habs2(sA[vox]));
            __half2 sb = sB[vox >> 1];
            float f3 = fabsf((vox & 1) ? __half2float(__high2half(sb))
                                       : __half2float(__low2half(sb)));
            float t1 = (float)((absT[0][w] >> (8 * j)) & 0xFFu);
            float t2 = (float)((absT[1][w] >> (8 * j)) & 0xFFu);
            float t3 = (float)((absT[2][w] >> (8 * j)) & 0xFFu);
            float d1 = f12.x - t1, d2 = f12.y - t2, d3 = f3 - t3;
            acc = fmaf(d1, d1, acc);
            acc = fmaf(d2, d2, acc);
            acc = fmaf(d3, d3, acc);
        }
    }

    // ---- block reduction -> double atomic -> last-block finalize ----
#pragma unroll
    for (int o = 16; o; o >>= 1) acc += __shfl_down_sync(0xffffffffu, acc, o);
    __shared__ float ws[8];
    __shared__ unsigned ticket;
    int lane = threadIdx.x & 31, wid = threadIdx.x >> 5;
    if (lane == 0) ws[wid] = acc;
    __syncthreads();
    if (wid == 0) {
        acc = (lane < 8) ? ws[lane] : 0.f;
#pragma unroll
        for (int o = 4; o; o >>= 1) acc += __shfl_down_sync(0xffffffffu, acc, o);
        if (lane == 0) {
            atomicAdd(&g_acc, (double)acc);
            __threadfence();
            ticket = atomicAdd(&g_done, 1u);
        }
    }
    __syncthreads();
    if (threadIdx.x == 0 && ticket == gridDim.x - 1) {
        double total = atomicAdd(&g_acc, 0.0);
        out[0] = (float)(total * (1.0 / NELEM));
        g_done = 0;
    }
}

extern "C" void kernel_launch(void* const* d_in, const int* in_sizes, int n_in,
                              void* d_out, int out_size) {
    const float* logits  = (const float*)d_in[0];
    const int*   targets = (const int*)d_in[1];
    float* out = (float*)d_out;

    softmax_kernel<<<NQ / 256, 256>>>(logits, targets);
    loss_kernel<<<NQ2 / 256, 256>>>(out);
}